// round 2
// baseline (speedup 1.0000x reference)
#include <cuda_runtime.h>
#include <math.h>

// ---------------------------------------------------------------------------
// VQ-VAE forward, fp32 direct implementation.
// Shapes: B=64, x[64,3,256,256]
//  enc: conv k4 s2 p1: 3->16 (128x128), 16->32 (64x64), 32->64 (32x32), BN+ReLU each
//  VQ:  65536 vectors of D=64 vs K=512 codes; loss = 2*mean(min ||z-c||^2)
//  dec: deconv k4 s2 p1: 64->32, 32->16, 16->3, BN+(ReLU,ReLU,tanh)
// Output: z_d (12,582,912 floats) then loss at out_size-1.
// ---------------------------------------------------------------------------

#define BB 64
static const float BN_EPS = 1e-5f;

// ------------------------- scratch (device globals) ------------------------
__device__ float g_a1[64 * 16 * 128 * 128]; // 16.7M
__device__ float g_a2[64 * 32 * 64 * 64];   // 8.4M
__device__ float g_a3[64 * 64 * 32 * 32];   // 4.2M  (z_e)
__device__ float g_q [64 * 64 * 32 * 32];   // 4.2M  (quantized, NCHW)
__device__ float g_d1[64 * 32 * 64 * 64];
__device__ float g_d2[64 * 16 * 128 * 128];

__device__ int    g_idx[65536];
__device__ float  g_codeNorm[512];
__device__ float2 g_part[64 * 32];   // bn partial sums (C<=64, split=32)
__device__ float  g_scale[64];
__device__ float  g_shift[64];
__device__ float  g_lossPart[512];

// ------------------------------ conv k4 s2 p1 ------------------------------
template <int CIN, int COUT, int HIN, int WIN>
__global__ __launch_bounds__(256)
void conv_k(const float* __restrict__ in, const float* __restrict__ w,
            const float* __restrict__ bias, float* __restrict__ out)
{
    constexpr int HOUT = HIN / 2, WOUT = WIN / 2;
    const int idx = blockIdx.x * 256 + threadIdx.x;
    constexpr long long total = (long long)BB * COUT * HOUT * WOUT;
    if (idx >= total) return;

    const int x = idx % WOUT;
    const int y = (idx / WOUT) % HOUT;
    const int o = (idx / (WOUT * HOUT)) % COUT;
    const int n = idx / (WOUT * HOUT * COUT);

    float acc = __ldg(&bias[o]);
    const float* inn = in + (long long)n * CIN * HIN * WIN;
    const float* wo  = w + o * CIN * 16;
    const int y0 = 2 * y - 1;
    const int x0 = 2 * x - 1;

    #pragma unroll
    for (int ky = 0; ky < 4; ky++) {
        const int yi = y0 + ky;
        if ((unsigned)yi >= (unsigned)HIN) continue;
        #pragma unroll 4
        for (int i = 0; i < CIN; i++) {
            const float* row = inn + (i * HIN + yi) * WIN;
            const float* wr  = wo + i * 16 + ky * 4;
            #pragma unroll
            for (int kx = 0; kx < 4; kx++) {
                const int xi = x0 + kx;
                if ((unsigned)xi < (unsigned)WIN)
                    acc = fmaf(__ldg(&row[xi]), __ldg(&wr[kx]), acc);
            }
        }
    }
    out[idx] = acc;
}

// --------------------------- deconv k4 s2 p1 -------------------------------
// y = conv(dilate2(in), w OIHW, pad=2)  (cross-correlation, no flip)
template <int CIN, int COUT, int HIN, int WIN>
__global__ __launch_bounds__(256)
void deconv_k(const float* __restrict__ in, const float* __restrict__ w,
              const float* __restrict__ bias, float* __restrict__ out)
{
    constexpr int HOUT = HIN * 2, WOUT = WIN * 2;
    const int idx = blockIdx.x * 256 + threadIdx.x;
    constexpr long long total = (long long)BB * COUT * HOUT * WOUT;
    if (idx >= total) return;

    const int x = idx % WOUT;
    const int y = (idx / WOUT) % HOUT;
    const int o = (idx / (WOUT * HOUT)) % COUT;
    const int n = idx / (WOUT * HOUT * COUT);

    // two taps per dimension, parity-dependent
    const int ky0 = (y & 1) ? 1 : 0;
    const int yi0 = (y - 2 + ky0) >> 1;       // arithmetic shift handles -2
    const int yi1 = yi0 + 1;                  // ky0+2
    const int kx0 = (x & 1) ? 1 : 0;
    const int xi0 = (x - 2 + kx0) >> 1;
    const int xi1 = xi0 + 1;

    const bool vy0 = ((unsigned)yi0 < (unsigned)HIN);
    const bool vy1 = ((unsigned)yi1 < (unsigned)HIN);
    const bool vx0 = ((unsigned)xi0 < (unsigned)WIN);
    const bool vx1 = ((unsigned)xi1 < (unsigned)WIN);

    float acc = __ldg(&bias[o]);
    const float* inn = in + (long long)n * CIN * HIN * WIN;
    const float* wo  = w + o * CIN * 16;

    #pragma unroll 4
    for (int i = 0; i < CIN; i++) {
        const float* chan = inn + i * HIN * WIN;
        const float* wi   = wo + i * 16;
        if (vy0) {
            const float* row = chan + yi0 * WIN;
            const float* wr  = wi + ky0 * 4;
            if (vx0) acc = fmaf(__ldg(&row[xi0]), __ldg(&wr[kx0]), acc);
            if (vx1) acc = fmaf(__ldg(&row[xi1]), __ldg(&wr[kx0 + 2]), acc);
        }
        if (vy1) {
            const float* row = chan + yi1 * WIN;
            const float* wr  = wi + (ky0 + 2) * 4;
            if (vx0) acc = fmaf(__ldg(&row[xi0]), __ldg(&wr[kx0]), acc);
            if (vx1) acc = fmaf(__ldg(&row[xi1]), __ldg(&wr[kx0 + 2]), acc);
        }
    }
    out[idx] = acc;
}

// ------------------------------- batchnorm ---------------------------------
// stage 1: grid = C*32 blocks of 256; block (c,s) reduces slab s of channel c
// chunk = HW/32 is divisible by 4 for all layers -> float4 loads
__global__ __launch_bounds__(256)
void bn_stats(const float* __restrict__ x, int C, int HW)
{
    const int c = blockIdx.x >> 5;
    const int s = blockIdx.x & 31;
    const int chunk4 = HW >> 7;   // (HW/32)/4 float4 elements

    float sum = 0.f, sq = 0.f;
    for (int n = 0; n < BB; n++) {
        const float4* base = (const float4*)(x + ((long long)(n * C + c)) * HW) +
                             s * chunk4;
        for (int p = threadIdx.x; p < chunk4; p += 256) {
            float4 v = base[p];
            sum += v.x + v.y + v.z + v.w;
            sq = fmaf(v.x, v.x, sq); sq = fmaf(v.y, v.y, sq);
            sq = fmaf(v.z, v.z, sq); sq = fmaf(v.w, v.w, sq);
        }
    }
    __shared__ float s1[256], s2[256];
    s1[threadIdx.x] = sum; s2[threadIdx.x] = sq;
    __syncthreads();
    for (int off = 128; off; off >>= 1) {
        if (threadIdx.x < off) {
            s1[threadIdx.x] += s1[threadIdx.x + off];
            s2[threadIdx.x] += s2[threadIdx.x + off];
        }
        __syncthreads();
    }
    if (threadIdx.x == 0) g_part[blockIdx.x] = make_float2(s1[0], s2[0]);
}

// stage 2: grid = C blocks of 32; compute scale/shift per channel
__global__ void bn_finalize(const float* __restrict__ gam,
                            const float* __restrict__ bet, int HW)
{
    const int c = blockIdx.x;
    float2 p = g_part[c * 32 + threadIdx.x];
    double S = p.x, Q = p.y;
    for (int off = 16; off; off >>= 1) {
        S += __shfl_down_sync(0xffffffffu, S, off);
        Q += __shfl_down_sync(0xffffffffu, Q, off);
    }
    if (threadIdx.x == 0) {
        const double P = (double)BB * (double)HW;
        const double mean = S / P;
        const double var  = Q / P - mean * mean;
        const float rstd  = (float)(1.0 / sqrt(var + (double)BN_EPS));
        const float sc = gam[c] * rstd;
        g_scale[c] = sc;
        g_shift[c] = bet[c] - (float)mean * sc;
    }
}

// stage 3: in-place affine + activation, float4. MODE 0 = relu, 1 = tanh
template <int MODE>
__global__ __launch_bounds__(256)
void bn_apply(float* __restrict__ x, int C, int HW, int total4)
{
    const int i = blockIdx.x * 256 + threadIdx.x;   // float4 index
    if (i >= total4) return;
    const int hw4 = HW >> 2;
    const int c = (i / hw4) % C;
    const float sc = g_scale[c], sh = g_shift[c];
    float4 v = ((float4*)x)[i];
    v.x = fmaf(v.x, sc, sh); v.y = fmaf(v.y, sc, sh);
    v.z = fmaf(v.z, sc, sh); v.w = fmaf(v.w, sc, sh);
    if (MODE == 0) {
        v.x = fmaxf(v.x, 0.f); v.y = fmaxf(v.y, 0.f);
        v.z = fmaxf(v.z, 0.f); v.w = fmaxf(v.w, 0.f);
    } else {
        v.x = tanhf(v.x); v.y = tanhf(v.y);
        v.z = tanhf(v.z); v.w = tanhf(v.w);
    }
    ((float4*)x)[i] = v;
}

// ---------------------------------- VQ -------------------------------------
__global__ void code_norms(const float* __restrict__ cb)
{
    const int k = threadIdx.x;  // 512 threads
    float s = 0.f;
    const float* r = cb + k * 64;
    #pragma unroll
    for (int d = 0; d < 64; d++) s = fmaf(r[d], r[d], s);
    g_codeNorm[k] = s;
}

__global__ __launch_bounds__(128)
void vq_argmin(const float* __restrict__ ze, const float* __restrict__ cb)
{
    __shared__ float sc[64 * 64];
    __shared__ float scn[64];
    __shared__ float red[128];

    const int idx = blockIdx.x * 128 + threadIdx.x; // 0..65535
    const int n  = idx >> 10;
    const int hw = idx & 1023;
    const float* base = ze + (long long)n * 64 * 1024 + hw;

    float z[64];
    float zz = 0.f;
    #pragma unroll
    for (int d = 0; d < 64; d++) { z[d] = base[d * 1024]; zz = fmaf(z[d], z[d], zz); }

    float best = 3.4e38f;
    int   bi   = 0;
    for (int ch = 0; ch < 8; ch++) {
        __syncthreads();
        for (int t = threadIdx.x; t < 4096; t += 128) sc[t] = cb[ch * 4096 + t];
        if (threadIdx.x < 64) scn[threadIdx.x] = g_codeNorm[ch * 64 + threadIdx.x];
        __syncthreads();
        for (int j = 0; j < 64; j++) {
            const float* cp = &sc[j * 64];
            float dot = 0.f;
            #pragma unroll
            for (int d = 0; d < 64; d++) dot = fmaf(z[d], cp[d], dot);
            const float dist = zz - 2.f * dot + scn[j];
            const int k = ch * 64 + j;
            if (dist < best) { best = dist; bi = k; }
        }
    }
    g_idx[idx] = bi;

    // exact squared distance of the chosen code (for the loss)
    const float* cr = cb + bi * 64;
    float e = 0.f;
    #pragma unroll
    for (int d = 0; d < 64; d++) { float df = z[d] - cr[d]; e = fmaf(df, df, e); }

    red[threadIdx.x] = e;
    __syncthreads();
    for (int off = 64; off; off >>= 1) {
        if (threadIdx.x < off) red[threadIdx.x] += red[threadIdx.x + off];
        __syncthreads();
    }
    if (threadIdx.x == 0) g_lossPart[blockIdx.x] = red[0];
}

__global__ void vq_loss_final(float* __restrict__ loss_out)
{
    __shared__ double red[512];
    red[threadIdx.x] = (double)g_lossPart[threadIdx.x];
    __syncthreads();
    for (int off = 256; off; off >>= 1) {
        if (threadIdx.x < off) red[threadIdx.x] += red[threadIdx.x + off];
        __syncthreads();
    }
    if (threadIdx.x == 0)
        loss_out[0] = (float)(2.0 * red[0] / (65536.0 * 64.0));
}

__global__ __launch_bounds__(256)
void vq_scatter(float* __restrict__ q, const float* __restrict__ cb)
{
    const int i = blockIdx.x * 256 + threadIdx.x; // 0 .. 4194303
    const int hw = i & 1023;
    const int d  = (i >> 10) & 63;
    const int n  = i >> 16;
    const int code = g_idx[n * 1024 + hw];
    q[i] = cb[code * 64 + d];
}

// -------------------------------- launch -----------------------------------
static inline int nblk(long long total) { return (int)((total + 255) / 256); }

extern "C" void kernel_launch(void* const* d_in, const int* in_sizes, int n_in,
                              void* d_out, int out_size)
{
    (void)in_sizes; (void)n_in;
    const float* x    = (const float*)d_in[0];
    const float* cb   = (const float*)d_in[1];
    const float* eW1  = (const float*)d_in[2];
    const float* eb1  = (const float*)d_in[3];
    const float* eg1  = (const float*)d_in[4];
    const float* ebt1 = (const float*)d_in[5];
    const float* eW2  = (const float*)d_in[6];
    const float* eb2  = (const float*)d_in[7];
    const float* eg2  = (const float*)d_in[8];
    const float* ebt2 = (const float*)d_in[9];
    const float* eW3  = (const float*)d_in[10];
    const float* eb3  = (const float*)d_in[11];
    const float* eg3  = (const float*)d_in[12];
    const float* ebt3 = (const float*)d_in[13];
    const float* dW1  = (const float*)d_in[14];
    const float* db1  = (const float*)d_in[15];
    const float* dg1  = (const float*)d_in[16];
    const float* dbt1 = (const float*)d_in[17];
    const float* dW2  = (const float*)d_in[18];
    const float* db2  = (const float*)d_in[19];
    const float* dg2  = (const float*)d_in[20];
    const float* dbt2 = (const float*)d_in[21];
    const float* dW3  = (const float*)d_in[22];
    const float* db3  = (const float*)d_in[23];
    const float* dg3  = (const float*)d_in[24];
    const float* dbt3 = (const float*)d_in[25];
    float* out = (float*)d_out;

    float *a1, *a2, *a3, *q, *d1, *d2;
    cudaGetSymbolAddress((void**)&a1, g_a1);
    cudaGetSymbolAddress((void**)&a2, g_a2);
    cudaGetSymbolAddress((void**)&a3, g_a3);
    cudaGetSymbolAddress((void**)&q,  g_q);
    cudaGetSymbolAddress((void**)&d1, g_d1);
    cudaGetSymbolAddress((void**)&d2, g_d2);

    // ---------------- encoder ----------------
    {   // conv1: 3->16, 256->128
        const long long T = (long long)BB * 16 * 128 * 128;
        conv_k<3, 16, 256, 256><<<nblk(T), 256>>>(x, eW1, eb1, a1);
        bn_stats<<<16 * 32, 256>>>(a1, 16, 128 * 128);
        bn_finalize<<<16, 32>>>(eg1, ebt1, 128 * 128);
        bn_apply<0><<<nblk(T / 4), 256>>>(a1, 16, 128 * 128, (int)(T / 4));
    }
    {   // conv2: 16->32, 128->64
        const long long T = (long long)BB * 32 * 64 * 64;
        conv_k<16, 32, 128, 128><<<nblk(T), 256>>>(a1, eW2, eb2, a2);
        bn_stats<<<32 * 32, 256>>>(a2, 32, 64 * 64);
        bn_finalize<<<32, 32>>>(eg2, ebt2, 64 * 64);
        bn_apply<0><<<nblk(T / 4), 256>>>(a2, 32, 64 * 64, (int)(T / 4));
    }
    {   // conv3: 32->64, 64->32  -> z_e
        const long long T = (long long)BB * 64 * 32 * 32;
        conv_k<32, 64, 64, 64><<<nblk(T), 256>>>(a2, eW3, eb3, a3);
        bn_stats<<<64 * 32, 256>>>(a3, 64, 32 * 32);
        bn_finalize<<<64, 32>>>(eg3, ebt3, 32 * 32);
        bn_apply<0><<<nblk(T / 4), 256>>>(a3, 64, 32 * 32, (int)(T / 4));
    }

    // ---------------- vector quantization ----------------
    code_norms<<<1, 512>>>(cb);
    vq_argmin<<<512, 128>>>(a3, cb);
    vq_loss_final<<<1, 512>>>(out + (out_size - 1));
    vq_scatter<<<nblk((long long)BB * 64 * 32 * 32), 256>>>(q, cb);

    // ---------------- decoder ----------------
    {   // deconv1: 64->32, 32->64
        const long long T = (long long)BB * 32 * 64 * 64;
        deconv_k<64, 32, 32, 32><<<nblk(T), 256>>>(q, dW1, db1, d1);
        bn_stats<<<32 * 32, 256>>>(d1, 32, 64 * 64);
        bn_finalize<<<32, 32>>>(dg1, dbt1, 64 * 64);
        bn_apply<0><<<nblk(T / 4), 256>>>(d1, 32, 64 * 64, (int)(T / 4));
    }
    {   // deconv2: 32->16, 64->128
        const long long T = (long long)BB * 16 * 128 * 128;
        deconv_k<32, 16, 64, 64><<<nblk(T), 256>>>(d1, dW2, db2, d2);
        bn_stats<<<16 * 32, 256>>>(d2, 16, 128 * 128);
        bn_finalize<<<16, 32>>>(dg2, dbt2, 128 * 128);
        bn_apply<0><<<nblk(T / 4), 256>>>(d2, 16, 128 * 128, (int)(T / 4));
    }
    {   // deconv3: 16->3, 128->256, BN + tanh, directly into d_out
        const long long T = (long long)BB * 3 * 256 * 256;
        deconv_k<16, 3, 128, 128><<<nblk(T), 256>>>(d2, dW3, db3, out);
        bn_stats<<<3 * 32, 256>>>(out, 3, 256 * 256);
        bn_finalize<<<3, 32>>>(dg3, dbt3, 256 * 256);
        bn_apply<1><<<nblk(T / 4), 256>>>(out, 3, 256 * 256, (int)T / 4);
    }
}

// round 3
// speedup vs baseline: 2.8948x; 2.8948x over previous
#include <cuda_runtime.h>
#include <math.h>

// ---------------------------------------------------------------------------
// VQ-VAE forward, fp32, co-group register blocking + smem weights.
// ---------------------------------------------------------------------------

#define BB 64
static const float BN_EPS = 1e-5f;

// ------------------------- scratch (device globals) ------------------------
__device__ float g_a1[64 * 16 * 128 * 128];
__device__ float g_a2[64 * 32 * 64 * 64];
__device__ float g_a3[64 * 64 * 32 * 32];
__device__ float g_q [64 * 64 * 32 * 32];
__device__ float g_d1[64 * 32 * 64 * 64];
__device__ float g_d2[64 * 16 * 128 * 128];

__device__ int    g_idx[65536];
__device__ float  g_codeNorm[512];
__device__ float2 g_part[64 * 32];
__device__ float  g_scale[64];
__device__ float  g_shift[64];
__device__ float  g_lossPart[512];

// ------------------------------ conv k4 s2 p1 ------------------------------
// One thread = one output pixel (n,y,x), COUTG output channels.
// grid.x = (BB*HOUT*WOUT)/256, grid.y = COUT/COUTG.
template <int CIN, int COUT, int COUTG, int CICHUNK, int HIN, int WIN>
__global__ __launch_bounds__(256)
void conv_k(const float* __restrict__ in, const float* __restrict__ w,
            const float* __restrict__ bias, float* __restrict__ out)
{
    constexpr int HOUT = HIN / 2, WOUT = WIN / 2;
    __shared__ float ws[COUTG * CICHUNK * 16];

    const int p = blockIdx.x * 256 + threadIdx.x;
    const int x = p % WOUT;
    const int y = (p / WOUT) % HOUT;
    const int n = p / (WOUT * HOUT);
    const int cog = blockIdx.y * COUTG;

    float acc[COUTG];
    #pragma unroll
    for (int j = 0; j < COUTG; j++) acc[j] = __ldg(&bias[cog + j]);

    const int y0 = 2 * y - 1;
    const int x0 = 2 * x - 1;
    const float* inn = in + (long long)n * CIN * HIN * WIN;

    for (int ci0 = 0; ci0 < CIN; ci0 += CICHUNK) {
        __syncthreads();
        // stage weights [COUTG][CICHUNK][16]
        for (int t = threadIdx.x; t < COUTG * CICHUNK * 16; t += 256) {
            const int co = t / (CICHUNK * 16);
            const int r  = t % (CICHUNK * 16);
            ws[t] = w[(cog + co) * CIN * 16 + ci0 * 16 + r];
        }
        __syncthreads();

        #pragma unroll
        for (int cil = 0; cil < CICHUNK; cil++) {
            const int ci = ci0 + cil;
            const float* chan = inn + (long long)ci * HIN * WIN;
            float tap[16];
            #pragma unroll
            for (int ky = 0; ky < 4; ky++) {
                const int yi = y0 + ky;
                const bool vy = ((unsigned)yi < (unsigned)HIN);
                const float* row = chan + yi * WIN;
                #pragma unroll
                for (int kx = 0; kx < 4; kx++) {
                    const int xi = x0 + kx;
                    const bool ok = vy && ((unsigned)xi < (unsigned)WIN);
                    tap[ky * 4 + kx] = ok ? __ldg(&row[xi]) : 0.f;
                }
            }
            const float* wb = ws + cil * 16;
            #pragma unroll
            for (int k = 0; k < 16; k++) {
                const float tv = tap[k];
                #pragma unroll
                for (int j = 0; j < COUTG; j++)
                    acc[j] = fmaf(tv, wb[j * CICHUNK * 16 + k], acc[j]);
            }
        }
    }

    #pragma unroll
    for (int j = 0; j < COUTG; j++)
        out[(((long long)n * COUT + cog + j) * HOUT + y) * WOUT + x] = acc[j];
}

// --------------------------- deconv k4 s2 p1 -------------------------------
// One thread = one output pixel, COUTG channels. 2x2 taps by parity.
template <int CIN, int COUT, int COUTG, int CICHUNK, int HIN, int WIN>
__global__ __launch_bounds__(256)
void deconv_k(const float* __restrict__ in, const float* __restrict__ w,
              const float* __restrict__ bias, float* __restrict__ out)
{
    constexpr int HOUT = HIN * 2, WOUT = WIN * 2;
    __shared__ float ws[COUTG * CICHUNK * 16];

    const int p = blockIdx.x * 256 + threadIdx.x;
    const int x = p % WOUT;
    const int y = (p / WOUT) % HOUT;
    const int n = p / (WOUT * HOUT);
    const int cog = blockIdx.y * COUTG;

    const int ky0 = (y & 1) ? 1 : 0;
    const int yi0 = (y - 2 + ky0) >> 1;
    const int yi1 = yi0 + 1;
    const int kx0 = (x & 1) ? 1 : 0;
    const int xi0 = (x - 2 + kx0) >> 1;
    const int xi1 = xi0 + 1;

    const bool vy0 = ((unsigned)yi0 < (unsigned)HIN);
    const bool vy1 = ((unsigned)yi1 < (unsigned)HIN);
    const bool vx0 = ((unsigned)xi0 < (unsigned)WIN);
    const bool vx1 = ((unsigned)xi1 < (unsigned)WIN);

    const int k00 = ky0 * 4 + kx0;
    const int k01 = ky0 * 4 + kx0 + 2;
    const int k10 = (ky0 + 2) * 4 + kx0;
    const int k11 = (ky0 + 2) * 4 + kx0 + 2;

    float acc[COUTG];
    #pragma unroll
    for (int j = 0; j < COUTG; j++) acc[j] = __ldg(&bias[cog + j]);

    const float* inn = in + (long long)n * CIN * HIN * WIN;

    for (int ci0 = 0; ci0 < CIN; ci0 += CICHUNK) {
        __syncthreads();
        for (int t = threadIdx.x; t < COUTG * CICHUNK * 16; t += 256) {
            const int co = t / (CICHUNK * 16);
            const int r  = t % (CICHUNK * 16);
            ws[t] = w[(cog + co) * CIN * 16 + ci0 * 16 + r];
        }
        __syncthreads();

        #pragma unroll
        for (int cil = 0; cil < CICHUNK; cil++) {
            const int ci = ci0 + cil;
            const float* chan = inn + (long long)ci * HIN * WIN;
            const float t00 = (vy0 && vx0) ? __ldg(&chan[yi0 * WIN + xi0]) : 0.f;
            const float t01 = (vy0 && vx1) ? __ldg(&chan[yi0 * WIN + xi1]) : 0.f;
            const float t10 = (vy1 && vx0) ? __ldg(&chan[yi1 * WIN + xi0]) : 0.f;
            const float t11 = (vy1 && vx1) ? __ldg(&chan[yi1 * WIN + xi1]) : 0.f;
            const float* wb = ws + cil * 16;
            #pragma unroll
            for (int j = 0; j < COUTG; j++) {
                const float* wj = wb + j * CICHUNK * 16;
                float a = acc[j];
                a = fmaf(t00, wj[k00], a);
                a = fmaf(t01, wj[k01], a);
                a = fmaf(t10, wj[k10], a);
                a = fmaf(t11, wj[k11], a);
                acc[j] = a;
            }
        }
    }

    #pragma unroll
    for (int j = 0; j < COUTG; j++)
        out[(((long long)n * COUT + cog + j) * HOUT + y) * WOUT + x] = acc[j];
}

// ------------------------------- batchnorm ---------------------------------
__global__ __launch_bounds__(256)
void bn_stats(const float* __restrict__ x, int C, int HW)
{
    const int c = blockIdx.x >> 5;
    const int s = blockIdx.x & 31;
    const int chunk4 = HW >> 7;

    float sum = 0.f, sq = 0.f;
    for (int n = 0; n < BB; n++) {
        const float4* base = (const float4*)(x + ((long long)(n * C + c)) * HW) +
                             s * chunk4;
        for (int p = threadIdx.x; p < chunk4; p += 256) {
            float4 v = base[p];
            sum += v.x + v.y + v.z + v.w;
            sq = fmaf(v.x, v.x, sq); sq = fmaf(v.y, v.y, sq);
            sq = fmaf(v.z, v.z, sq); sq = fmaf(v.w, v.w, sq);
        }
    }
    __shared__ float s1[256], s2[256];
    s1[threadIdx.x] = sum; s2[threadIdx.x] = sq;
    __syncthreads();
    for (int off = 128; off; off >>= 1) {
        if (threadIdx.x < off) {
            s1[threadIdx.x] += s1[threadIdx.x + off];
            s2[threadIdx.x] += s2[threadIdx.x + off];
        }
        __syncthreads();
    }
    if (threadIdx.x == 0) g_part[blockIdx.x] = make_float2(s1[0], s2[0]);
}

__global__ void bn_finalize(const float* __restrict__ gam,
                            const float* __restrict__ bet, int HW)
{
    const int c = blockIdx.x;
    float2 p = g_part[c * 32 + threadIdx.x];
    double S = p.x, Q = p.y;
    for (int off = 16; off; off >>= 1) {
        S += __shfl_down_sync(0xffffffffu, S, off);
        Q += __shfl_down_sync(0xffffffffu, Q, off);
    }
    if (threadIdx.x == 0) {
        const double P = (double)BB * (double)HW;
        const double mean = S / P;
        const double var  = Q / P - mean * mean;
        const float rstd  = (float)(1.0 / sqrt(var + (double)BN_EPS));
        const float sc = gam[c] * rstd;
        g_scale[c] = sc;
        g_shift[c] = bet[c] - (float)mean * sc;
    }
}

template <int MODE>
__global__ __launch_bounds__(256)
void bn_apply(float* __restrict__ x, int C, int HW, int total4)
{
    const int i = blockIdx.x * 256 + threadIdx.x;
    if (i >= total4) return;
    const int hw4 = HW >> 2;
    const int c = (i / hw4) % C;
    const float sc = g_scale[c], sh = g_shift[c];
    float4 v = ((float4*)x)[i];
    v.x = fmaf(v.x, sc, sh); v.y = fmaf(v.y, sc, sh);
    v.z = fmaf(v.z, sc, sh); v.w = fmaf(v.w, sc, sh);
    if (MODE == 0) {
        v.x = fmaxf(v.x, 0.f); v.y = fmaxf(v.y, 0.f);
        v.z = fmaxf(v.z, 0.f); v.w = fmaxf(v.w, 0.f);
    } else {
        v.x = tanhf(v.x); v.y = tanhf(v.y);
        v.z = tanhf(v.z); v.w = tanhf(v.w);
    }
    ((float4*)x)[i] = v;
}

// ---------------------------------- VQ -------------------------------------
__global__ void code_norms(const float* __restrict__ cb)
{
    const int k = threadIdx.x;
    float s = 0.f;
    const float* r = cb + k * 64;
    #pragma unroll
    for (int d = 0; d < 64; d++) s = fmaf(r[d], r[d], s);
    g_codeNorm[k] = s;
}

__global__ __launch_bounds__(128)
void vq_argmin(const float* __restrict__ ze, const float* __restrict__ cb)
{
    __shared__ float sc[64 * 64];
    __shared__ float scn[64];
    __shared__ float red[128];

    const int idx = blockIdx.x * 128 + threadIdx.x;
    const int n  = idx >> 10;
    const int hw = idx & 1023;
    const float* base = ze + (long long)n * 64 * 1024 + hw;

    float z[64];
    #pragma unroll
    for (int d = 0; d < 64; d++) z[d] = base[d * 1024];
    float zz = 0.f;
    #pragma unroll
    for (int d = 0; d < 64; d++) zz = fmaf(z[d], z[d], zz);

    float best = 3.4e38f;
    int   bi   = 0;
    for (int ch = 0; ch < 8; ch++) {
        __syncthreads();
        for (int t = threadIdx.x; t < 1024; t += 128)
            ((float4*)sc)[t] = ((const float4*)(cb + ch * 4096))[t];
        if (threadIdx.x < 64) scn[threadIdx.x] = g_codeNorm[ch * 64 + threadIdx.x];
        __syncthreads();
        #pragma unroll 2
        for (int j = 0; j < 64; j++) {
            const float4* cp = (const float4*)&sc[j * 64];
            float dot = 0.f;
            #pragma unroll
            for (int d4 = 0; d4 < 16; d4++) {
                float4 c4 = cp[d4];
                dot = fmaf(z[4*d4+0], c4.x, dot);
                dot = fmaf(z[4*d4+1], c4.y, dot);
                dot = fmaf(z[4*d4+2], c4.z, dot);
                dot = fmaf(z[4*d4+3], c4.w, dot);
            }
            const float dist = zz - 2.f * dot + scn[j];
            const int k = ch * 64 + j;
            if (dist < best) { best = dist; bi = k; }
        }
    }
    g_idx[idx] = bi;

    const float* cr = cb + bi * 64;
    float e = 0.f;
    #pragma unroll
    for (int d = 0; d < 64; d++) { float df = z[d] - cr[d]; e = fmaf(df, df, e); }

    red[threadIdx.x] = e;
    __syncthreads();
    for (int off = 64; off; off >>= 1) {
        if (threadIdx.x < off) red[threadIdx.x] += red[threadIdx.x + off];
        __syncthreads();
    }
    if (threadIdx.x == 0) g_lossPart[blockIdx.x] = red[0];
}

__global__ void vq_loss_final(float* __restrict__ loss_out)
{
    __shared__ double red[512];
    red[threadIdx.x] = (double)g_lossPart[threadIdx.x];
    __syncthreads();
    for (int off = 256; off; off >>= 1) {
        if (threadIdx.x < off) red[threadIdx.x] += red[threadIdx.x + off];
        __syncthreads();
    }
    if (threadIdx.x == 0)
        loss_out[0] = (float)(2.0 * red[0] / (65536.0 * 64.0));
}

__global__ __launch_bounds__(256)
void vq_scatter(float* __restrict__ q, const float* __restrict__ cb)
{
    const int i = blockIdx.x * 256 + threadIdx.x;
    const int hw = i & 1023;
    const int d  = (i >> 10) & 63;
    const int n  = i >> 16;
    const int code = g_idx[n * 1024 + hw];
    q[i] = cb[code * 64 + d];
}

// -------------------------------- launch -----------------------------------
static inline int nblk(long long total) { return (int)((total + 255) / 256); }

extern "C" void kernel_launch(void* const* d_in, const int* in_sizes, int n_in,
                              void* d_out, int out_size)
{
    (void)in_sizes; (void)n_in;
    const float* x    = (const float*)d_in[0];
    const float* cb   = (const float*)d_in[1];
    const float* eW1  = (const float*)d_in[2];
    const float* eb1  = (const float*)d_in[3];
    const float* eg1  = (const float*)d_in[4];
    const float* ebt1 = (const float*)d_in[5];
    const float* eW2  = (const float*)d_in[6];
    const float* eb2  = (const float*)d_in[7];
    const float* eg2  = (const float*)d_in[8];
    const float* ebt2 = (const float*)d_in[9];
    const float* eW3  = (const float*)d_in[10];
    const float* eb3  = (const float*)d_in[11];
    const float* eg3  = (const float*)d_in[12];
    const float* ebt3 = (const float*)d_in[13];
    const float* dW1  = (const float*)d_in[14];
    const float* db1  = (const float*)d_in[15];
    const float* dg1  = (const float*)d_in[16];
    const float* dbt1 = (const float*)d_in[17];
    const float* dW2  = (const float*)d_in[18];
    const float* db2  = (const float*)d_in[19];
    const float* dg2  = (const float*)d_in[20];
    const float* dbt2 = (const float*)d_in[21];
    const float* dW3  = (const float*)d_in[22];
    const float* db3  = (const float*)d_in[23];
    const float* dg3  = (const float*)d_in[24];
    const float* dbt3 = (const float*)d_in[25];
    float* out = (float*)d_out;

    float *a1, *a2, *a3, *q, *d1, *d2;
    cudaGetSymbolAddress((void**)&a1, g_a1);
    cudaGetSymbolAddress((void**)&a2, g_a2);
    cudaGetSymbolAddress((void**)&a3, g_a3);
    cudaGetSymbolAddress((void**)&q,  g_q);
    cudaGetSymbolAddress((void**)&d1, g_d1);
    cudaGetSymbolAddress((void**)&d2, g_d2);

    // ---------------- encoder ----------------
    {   // conv1: 3->16, 256->128; pixels = 64*128*128 = 1,048,576
        const long long T = (long long)BB * 16 * 128 * 128;
        dim3 grid(1048576 / 256, 1);
        conv_k<3, 16, 16, 3, 256, 256><<<grid, 256>>>(x, eW1, eb1, a1);
        bn_stats<<<16 * 32, 256>>>(a1, 16, 128 * 128);
        bn_finalize<<<16, 32>>>(eg1, ebt1, 128 * 128);
        bn_apply<0><<<nblk(T / 4), 256>>>(a1, 16, 128 * 128, (int)(T / 4));
    }
    {   // conv2: 16->32, 128->64; pixels = 64*64*64 = 262,144
        const long long T = (long long)BB * 32 * 64 * 64;
        dim3 grid(262144 / 256, 1);
        conv_k<16, 32, 32, 8, 128, 128><<<grid, 256>>>(a1, eW2, eb2, a2);
        bn_stats<<<32 * 32, 256>>>(a2, 32, 64 * 64);
        bn_finalize<<<32, 32>>>(eg2, ebt2, 64 * 64);
        bn_apply<0><<<nblk(T / 4), 256>>>(a2, 32, 64 * 64, (int)(T / 4));
    }
    {   // conv3: 32->64, 64->32; pixels = 64*32*32 = 65,536; 2 co-groups
        const long long T = (long long)BB * 64 * 32 * 32;
        dim3 grid(65536 / 256, 2);
        conv_k<32, 64, 32, 8, 64, 64><<<grid, 256>>>(a2, eW3, eb3, a3);
        bn_stats<<<64 * 32, 256>>>(a3, 64, 32 * 32);
        bn_finalize<<<64, 32>>>(eg3, ebt3, 32 * 32);
        bn_apply<0><<<nblk(T / 4), 256>>>(a3, 64, 32 * 32, (int)(T / 4));
    }

    // ---------------- vector quantization ----------------
    code_norms<<<1, 512>>>(cb);
    vq_argmin<<<512, 128>>>(a3, cb);
    vq_loss_final<<<1, 512>>>(out + (out_size - 1));
    vq_scatter<<<nblk((long long)BB * 64 * 32 * 32), 256>>>(q, cb);

    // ---------------- decoder ----------------
    {   // deconv1: 64->32, 32->64; out pixels = 64*64*64 = 262,144
        const long long T = (long long)BB * 32 * 64 * 64;
        dim3 grid(262144 / 256, 1);
        deconv_k<64, 32, 32, 8, 32, 32><<<grid, 256>>>(q, dW1, db1, d1);
        bn_stats<<<32 * 32, 256>>>(d1, 32, 64 * 64);
        bn_finalize<<<32, 32>>>(dg1, dbt1, 64 * 64);
        bn_apply<0><<<nblk(T / 4), 256>>>(d1, 32, 64 * 64, (int)(T / 4));
    }
    {   // deconv2: 32->16, 64->128; out pixels = 64*128*128 = 1,048,576
        const long long T = (long long)BB * 16 * 128 * 128;
        dim3 grid(1048576 / 256, 1);
        deconv_k<32, 16, 16, 16, 64, 64><<<grid, 256>>>(d1, dW2, db2, d2);
        bn_stats<<<16 * 32, 256>>>(d2, 16, 128 * 128);
        bn_finalize<<<16, 32>>>(dg2, dbt2, 128 * 128);
        bn_apply<0><<<nblk(T / 4), 256>>>(d2, 16, 128 * 128, (int)(T / 4));
    }
    {   // deconv3: 16->3, 128->256; out pixels = 64*256*256 = 4,194,304
        const long long T = (long long)BB * 3 * 256 * 256;
        dim3 grid(4194304 / 256, 1);
        deconv_k<16, 3, 3, 16, 128, 128><<<grid, 256>>>(d2, dW3, db3, out);
        bn_stats<<<3 * 32, 256>>>(out, 3, 256 * 256);
        bn_finalize<<<3, 32>>>(dg3, dbt3, 256 * 256);
        bn_apply<1><<<nblk(T / 4), 256>>>(out, 3, 256 * 256, (int)T / 4);
    }
}